// round 12
// baseline (speedup 1.0000x reference)
#include <cuda_runtime.h>
#include <cuda_fp16.h>

// Problem constants
#define NB 16            // batch B
#define TT 12            // T_IN
#define TO 24            // T_TOTAL
#define NN 5000          // nodes
#define CC 4             // channels
#define KK 16            // neighbors
#define HH 4             // heads
#define BT (NB * TT)     // 192
#define DIN (TT * HH)    // 48
#define DOUT (TO - TT)   // 12
#define NT 2             // nodes per block
#define THREADS 384
#define A_STRIDE 56      // halves per A row (112B = 7*16B -> conflict-free ldmatrix)
#define XG_ROW 776       // halves per Xg row (1552B = 97*16B -> conflict-free trans-ldmatrix)

// Scratch: x transposed+converted to fp16: [N][bt] = (c01,c23). 7.68 MB, L2-resident.
__device__ uint2 g_xt2[NN * BT];

static __device__ __forceinline__ unsigned sm32(const void* p) {
    return (unsigned)__cvta_generic_to_shared(p);
}

// ---------------------------------------------------------------------------
// Kernel 1: x [B,T,N,C] f32 -> g_xt2 [N][bt] fp16 (transposed)  AND out[:, :12] = x
// (at DRAM roofline: 38.4 MB total traffic)
// ---------------------------------------------------------------------------
__global__ void __launch_bounds__(1024) transpose_convert_kernel(
    const float* __restrict__ x, float* __restrict__ out)
{
    __shared__ uint2 tile[32][33];
    const float4* __restrict__ x4 = (const float4*)x;
    float4* __restrict__ out4 = (float4*)out;

    int tx = threadIdx.x, ty = threadIdx.y;
    int n  = blockIdx.x * 32 + tx;
    int bt = blockIdx.y * 32 + ty;          // gridDim.y*32 == 192 exactly

    if (n < NN) {
        float4 v = x4[bt * NN + n];
        __half2 h01 = __floats2half2_rn(v.x, v.y);
        __half2 h23 = __floats2half2_rn(v.z, v.w);
        uint2 u;
        u.x = *reinterpret_cast<unsigned*>(&h01);
        u.y = *reinterpret_cast<unsigned*>(&h23);
        tile[ty][tx] = u;
        int b = bt / TT, t = bt - b * TT;
        out4[(b * TO + t) * NN + n] = v;    // out[:, :12] = x (coalesced)
    }
    __syncthreads();

    int n2  = blockIdx.x * 32 + ty;
    int bt2 = blockIdx.y * 32 + tx;
    if (n2 < NN) {
        g_xt2[n2 * BT + bt2] = tile[tx][ty];   // 256B/warp coalesced
    }
}

// ---------------------------------------------------------------------------
// Kernel 2: per node-pair, BOTH stages on tensor cores.
//   per node: gather neighbor rows into Xg[k][m] (m = bt*4+c, fp16, k-major)
//             agg[(bt,c), h] = Xg^T @ w  via 48x mma.m16n8k16 (trans-ldmatrix A)
//             D frags -> fp16 A_s tile (rows nl*64+b*4+c, cols t*4+h)
//   phase 2:  D[128,12] = A_s[128,48] @ W[48,12] via mma (warps 0-7)
//   epilogue: bias + ReLU, staged coalesced float4 stores
// ---------------------------------------------------------------------------
__global__ void __launch_bounds__(THREADS, 4) gnn_main_kernel(
    const float* __restrict__ dists, const int* __restrict__ neighbors,
    const float* __restrict__ W, const float* __restrict__ bias,
    float* __restrict__ out)
{
    __shared__ __align__(16) __half A_s[128 * A_STRIDE];   // 14336B
    __shared__ __align__(16) __half WT_s[16 * A_STRIDE];   // 1792B  (W^T rows o, cols th)
    __shared__ __align__(16) __half Xg[KK * XG_ROW];       // 24832B (one node at a time)
    __shared__ __align__(16) __half wT_s[NT][8 * KK];      // 512B   (w^T rows h(8), cols k)
    __shared__ int   nbr_s[NT][KK];
    __shared__ float b_s[DOUT];
    __shared__ __align__(16) float ys2[384 * 4];           // 6144B

    const int tid  = threadIdx.x;             // 0..383
    const int n0   = blockIdx.x * NT;
    const int lane = tid & 31;
    const int w    = tid >> 5;                // 0..11
    const int gID  = lane >> 2;
    const int tig  = lane & 3;

    // --- Phase 0 ---
    if (tid < NT * KK) {
        int nn = tid >> 4, k = tid & 15;
        float d = dists[(n0 + nn) * KK + k];
        nbr_s[nn][k] = neighbors[(n0 + nn) * KK + k] * BT;   // pre-scaled
        float p = d * d * (1.0f / 36.0f);     // d^2 / sigma^2
        wT_s[nn][0 * KK + k] = __float2half(__expf(-0.25f * p));
        wT_s[nn][1 * KK + k] = __float2half(__expf(-0.50f * p));
        wT_s[nn][2 * KK + k] = __float2half(__expf(-0.75f * p));
        wT_s[nn][3 * KK + k] = __float2half(__expf(-p));
        wT_s[nn][4 * KK + k] = __half(0.f);   // pad heads 4-7 = 0
        wT_s[nn][5 * KK + k] = __half(0.f);
        wT_s[nn][6 * KK + k] = __half(0.f);
        wT_s[nn][7 * KK + k] = __half(0.f);
    }
    #pragma unroll
    for (int i = tid; i < DIN * DOUT; i += THREADS) {
        int th = i / DOUT, o = i - th * DOUT;
        WT_s[o * A_STRIDE + th] = __float2half(W[i]);      // W^T, fp16
    }
    if (tid < DOUT) b_s[tid] = bias[tid];
    __syncthreads();

    // Lane-invariant trans-ldmatrix base: lane groups -> (krow, m-offset)
    // grp0: k j,   m+0 -> (M0-7 ,K0-7 )   grp1: k j,   m+8 -> (M8-15,K0-7 )
    // grp2: k j+8, m+0 -> (M0-7 ,K8-15)   grp3: k j+8, m+8 -> (M8-15,K8-15)
    const int grp = lane >> 3, j = lane & 7;
    const unsigned xg_lane = sm32(Xg)
        + (unsigned)(j + ((grp & 2) ? 8 : 0)) * (XG_ROW * 2)
        + ((grp & 1) ? 16u : 0u);

    // gather decomposition: tid = q*192 + r  ->  k = 2*i+q, bt = r
    const int q = tid / BT;                   // 0..1 (warp-uniform)
    const int r = tid - q * BT;

    #pragma unroll
    for (int node = 0; node < NT; ++node) {
        // --- Gather: fill Xg[k][m], m = bt*4 + c. 256B/warp LDG + STS, all coalesced.
        #pragma unroll
        for (int i = 0; i < 8; ++i) {
            int k = 2 * i + q;
            uint2 v = g_xt2[nbr_s[node][k] + r];
            *(uint2*)&Xg[k * XG_ROW + r * 4] = v;
        }
        __syncthreads();

        // --- Aggregation MMA: 48 m16-tiles, 4 per warp.
        unsigned bw0 = *(const unsigned*)&wT_s[node][gID * KK + tig * 2];
        unsigned bw1 = *(const unsigned*)&wT_s[node][gID * KK + tig * 2 + 8];

        #pragma unroll
        for (int i = 0; i < 4; ++i) {
            int T = w * 4 + i;                // 0..47 ; m rows [T*16, T*16+16)
            unsigned a0, a1, a2, a3;
            asm volatile(
                "ldmatrix.sync.aligned.m8n8.x4.trans.shared.b16 {%0,%1,%2,%3}, [%4];"
                : "=r"(a0), "=r"(a1), "=r"(a2), "=r"(a3)
                : "r"(xg_lane + (unsigned)T * 32u));
            float d0 = 0.f, d1 = 0.f, d2 = 0.f, d3 = 0.f;
            asm volatile(
                "mma.sync.aligned.m16n8k16.row.col.f32.f16.f16.f32 "
                "{%0,%1,%2,%3}, {%4,%5,%6,%7}, {%8,%9}, {%0,%1,%2,%3};"
                : "+f"(d0), "+f"(d1), "+f"(d2), "+f"(d3)
                : "r"(a0), "r"(a1), "r"(a2), "r"(a3), "r"(bw0), "r"(bw1));

            if (tig < 2) {                    // h = tig*2, tig*2+1 valid
                int m  = T * 16 + gID;        // row m of D
                int bt = m >> 2, c = m & 3;
                int b  = bt / TT, t = bt - b * TT;
                *(__half2*)&A_s[(node * 64 + b * 4 + c) * A_STRIDE + t * 4 + tig * 2]
                    = __floats2half2_rn(d0, d1);
                int m2  = m + 8;
                int bt2 = m2 >> 2, c2 = m2 & 3;
                int b2  = bt2 / TT, t2 = bt2 - b2 * TT;
                *(__half2*)&A_s[(node * 64 + b2 * 4 + c2) * A_STRIDE + t2 * 4 + tig * 2]
                    = __floats2half2_rn(d2, d3);
            }
        }
        __syncthreads();                      // Xg free for next node / A_s ready
    }

    // --- Phase 2: tensor-core matmul. Warps 0-7 own one m16-tile each. ---
    if (w < 8) {
        // B fragments: W^T[n][k] pairs (validated layout).
        unsigned bf[2][3][2];
        #pragma unroll
        for (int nt = 0; nt < 2; ++nt)
            #pragma unroll
            for (int s = 0; s < 3; ++s) {
                int n = nt * 8 + gID;
                bf[nt][s][0] = *(const unsigned*)&WT_s[n * A_STRIDE + s * 16 + tig * 2];
                bf[nt][s][1] = *(const unsigned*)&WT_s[n * A_STRIDE + s * 16 + tig * 2 + 8];
            }

        float d0[4] = {0.f, 0.f, 0.f, 0.f};
        float d1[4] = {0.f, 0.f, 0.f, 0.f};

        unsigned abase = sm32(A_s) +
            (w * 16 + (lane & 15)) * (A_STRIDE * 2) + (lane >> 4) * 16;
        #pragma unroll
        for (int s = 0; s < 3; ++s) {
            unsigned a0, a1, a2, a3;
            asm volatile(
                "ldmatrix.sync.aligned.m8n8.x4.shared.b16 {%0,%1,%2,%3}, [%4];"
                : "=r"(a0), "=r"(a1), "=r"(a2), "=r"(a3)
                : "r"(abase + s * 32));
            asm volatile(
                "mma.sync.aligned.m16n8k16.row.col.f32.f16.f16.f32 "
                "{%0,%1,%2,%3}, {%4,%5,%6,%7}, {%8,%9}, {%0,%1,%2,%3};"
                : "+f"(d0[0]), "+f"(d0[1]), "+f"(d0[2]), "+f"(d0[3])
                : "r"(a0), "r"(a1), "r"(a2), "r"(a3),
                  "r"(bf[0][s][0]), "r"(bf[0][s][1]));
            asm volatile(
                "mma.sync.aligned.m16n8k16.row.col.f32.f16.f16.f32 "
                "{%0,%1,%2,%3}, {%4,%5,%6,%7}, {%8,%9}, {%0,%1,%2,%3};"
                : "+f"(d1[0]), "+f"(d1[1]), "+f"(d1[2]), "+f"(d1[3])
                : "r"(a0), "r"(a1), "r"(a2), "r"(a3),
                  "r"(bf[1][s][0]), "r"(bf[1][s][1]));
        }

        // Epilogue: bias + ReLU, stage to ys2.
        #pragma unroll
        for (int nt = 0; nt < 2; ++nt) {
            const float* dd = nt ? d1 : d0;
            #pragma unroll
            for (int i = 0; i < 4; ++i) {
                int o = nt * 8 + tig * 2 + (i & 1);
                if (o < DOUT) {
                    int row = w * 16 + gID + (i >> 1) * 8;   // nl*64 + b*4 + c
                    int nl2 = row >> 6, bb = (row >> 2) & 15, cc = row & 3;
                    float val = fmaxf(dd[i] + b_s[o], 0.f);
                    ys2[(((bb * DOUT + o) << 1) + nl2) * 4 + cc] = val;
                }
            }
        }
    }
    __syncthreads();

    // --- Coalesced float4 stores: 384 cells / 384 threads = 1 each ---
    {
        float4* __restrict__ out4 = (float4*)out;
        int cell = tid >> 1, jn = tid & 1;       // cell = b*12+o, jn = node
        int bb = cell / DOUT, oo = cell - bb * DOUT;
        float4 v = *(const float4*)&ys2[tid * 4];
        out4[(bb * TO + TT + oo) * NN + n0 + jn] = v;
    }
}

// ---------------------------------------------------------------------------
// metadata order: x (f32), dists (f32), W (f32), b (f32), neighbors (i32);
// output f32 (7680000)
// ---------------------------------------------------------------------------
extern "C" void kernel_launch(void* const* d_in, const int* in_sizes, int n_in,
                              void* d_out, int out_size)
{
    const float* x         = (const float*)d_in[0];
    const float* dists     = (const float*)d_in[1];
    const float* W         = (const float*)d_in[2];
    const float* bias      = (const float*)d_in[3];
    const int*   neighbors = (const int*)d_in[4];
    float* out = (float*)d_out;

    dim3 tb(32, 32);
    dim3 tg((NN + 31) / 32, BT / 32);        // 157 x 6
    transpose_convert_kernel<<<tg, tb>>>(x, out);

    gnn_main_kernel<<<NN / NT, THREADS>>>(dists, neighbors, W, bias, out);
}